// round 8
// baseline (speedup 1.0000x reference)
#include <cuda_runtime.h>
#include <cuda_bf16.h>
#include <math.h>

// ---------------------------------------------------------------------------
// Problem constants
// ---------------------------------------------------------------------------
#define B        8
#define CIN      15          // 3*5 after reshape
#define C1       64
#define H0       512
#define W0       512
#define H1       256
#define W1       256
#define C2       128
#define H2       128
#define W2       128
#define NE       3
#define CONV1_K  (CIN*7*7)   // 735
#define CONV1_KA (8*49)      // 392 (ic 0..7)
#define CONV1_KB (7*49)      // 343 (ic 8..14)
#define CONV2_K  (C1*3*3)    // 576
#define HEAD1_K  (C2*3*3)    // 1152
#define HEAD1_KH (64*3*3)    // 576 (one ic-half)

// Deinterleaved padded input: per row [even 260 | odd 260] floats, 520 rows.
#define XW  520
#define XR  520
// ebuf1 (conv1 out, 256x256) deinterleaved: row = iy+1 (258 rows),
// [even 128 | odd 132] = 260 floats
#define E1R 258
#define E1W 260
// ebuf2 (conv2 out, 128x128) padded plain: 130 rows x 132, interior 1..128
#define E2R 130
#define E2W 132

// ---------------------------------------------------------------------------
// Device scratch
// ---------------------------------------------------------------------------
__device__ __align__(16) float d_xpad  [(long)B*CIN*XR*XW];
__device__ __align__(16) float d_gbuf  [(long)B*C1*H1*W1];
__device__ __align__(16) float d_ebuf1p[(long)B*C1*E1R*E1W];
__device__ __align__(16) float d_ebuf2p[(long)B*C2*E2R*E2W];
__device__ __align__(16) float d_ebuf3 [(long)B*C2*H2*W2];
__device__ float d_pooled[B*C1];
__device__ int   d_eidx[B];

// ---------------------------------------------------------------------------
// Packed f32x2 helpers
// ---------------------------------------------------------------------------
__device__ __forceinline__ unsigned long long pack2(float v) {
    unsigned long long r;
    asm("mov.b64 %0, {%1, %1};" : "=l"(r) : "f"(v));
    return r;
}
__device__ __forceinline__ void ffma2(unsigned long long& d,
                                      unsigned long long a,
                                      unsigned long long b) {
    asm("fma.rn.f32x2 %0, %1, %2, %0;" : "+l"(d) : "l"(a), "l"(b));
}
__device__ __forceinline__ float f2lo(unsigned long long v) {
    return __uint_as_float((unsigned int)v);
}
__device__ __forceinline__ float f2hi(unsigned long long v) {
    return __uint_as_float((unsigned int)(v >> 32));
}

#define FFMA2_16(accp, vv, wA, wB, wC, wD) do {                       \
    ffma2((accp)[0], (vv), (wA).x); ffma2((accp)[1], (vv), (wA).y);   \
    ffma2((accp)[2], (vv), (wB).x); ffma2((accp)[3], (vv), (wB).y);   \
    ffma2((accp)[4], (vv), (wC).x); ffma2((accp)[5], (vv), (wC).y);   \
    ffma2((accp)[6], (vv), (wD).x); ffma2((accp)[7], (vv), (wD).y);   \
} while (0)

// ---------------------------------------------------------------------------
// Kernel 0: prep — pad/deinterleave input + zero activation halos (one launch)
// ---------------------------------------------------------------------------
#define PREP_X   (B*CIN*XR)
#define PREP_E1  (PREP_X + B*C1)
#define PREP_E2  (PREP_E1 + B*C2)

__global__ void __launch_bounds__(256)
prep_kernel(const float* __restrict__ x)
{
    const int blk = blockIdx.x;
    const int t   = threadIdx.x;
    if (blk < PREP_X) {
        const int bc = blk / XR;
        const int r  = blk - bc * XR;
        const int iy = r - 3;
        float* dst = d_xpad + (long)blk * XW;
        const bool rowok = (unsigned)iy < (unsigned)H0;
        if (!rowok) {
            for (int c = t; c < XW; c += 256) dst[c] = 0.f;
        } else {
            const float* src = x + (long)bc * (H0 * W0) + (long)iy * W0;
            if (t < 128) {
                const float4 v = *(const float4*)(src + 4 * t);
                dst[1 + 2 * t]       = v.x;   // even plane, e=2t
                dst[2 + 2 * t]       = v.z;   // even plane, e=2t+1
                dst[260 + 2 + 2 * t] = v.y;   // odd plane,  o=2t
                dst[260 + 3 + 2 * t] = v.w;   // odd plane,  o=2t+1
            } else if (t == 128) {
                dst[0] = 0.f; dst[257] = 0.f; dst[258] = 0.f; dst[259] = 0.f;
                dst[260] = 0.f; dst[261] = 0.f; dst[518] = 0.f; dst[519] = 0.f;
            }
        }
    } else if (blk < PREP_E1) {
        float* p = d_ebuf1p + (long)(blk - PREP_X) * (E1R * E1W);
        for (int i = t; i < E1W; i += 256) p[i] = 0.f;      // row 0
        {
            float* r = p + (t + 1) * E1W;                   // rows 1..256
            r[128] = 0.f;
            r[257] = 0.f; r[258] = 0.f; r[259] = 0.f;
        }
    } else {
        float* p = d_ebuf2p + (long)(blk - PREP_E1) * (E2R * E2W);
        for (int i = t; i < E2W; i += 256) {
            p[i] = 0.f;                                     // row 0
            p[129 * E2W + i] = 0.f;                         // row 129
        }
        if (t < 128) {
            float* r = p + (t + 1) * E2W;                   // rows 1..128
            r[0] = 0.f; r[129] = 0.f; r[130] = 0.f; r[131] = 0.f;
        }
    }
}

// ---------------------------------------------------------------------------
// Kernel 1: 7x7 s2 conv, 15 -> 64, deinterleaved padded input.
// Block 128 thr = 2 output rows x 64 lanes; lane computes 4 px, 16 oc.
// Weights staged in TWO passes (ic 0..7, 8..14) -> 25KB smem, 5 blocks/SM.
// Grid (128, 4, 8).
// ---------------------------------------------------------------------------
template <bool GATING>
__global__ void __launch_bounds__(128, 5)
conv7x7_kernel(const float* __restrict__ w_all,
               const float* __restrict__ bn_gamma,
               const float* __restrict__ bn_beta,
               const float* __restrict__ bn_mean,
               const float* __restrict__ bn_var)
{
    const int oy  = blockIdx.x * 2 + (threadIdx.x >> 6);
    const int ocg = blockIdx.y;
    const int b   = blockIdx.z;
    const int l   = threadIdx.x & 63;

    const float* w = w_all + (long)ocg * 16 * CONV1_K;
    if (!GATING) w += (long)d_eidx[b] * (C1 * CONV1_K);

    __shared__ __align__(16) float wsm[CONV1_KA][16];      // 25088 B

    unsigned long long acc[4][8];
#pragma unroll
    for (int p = 0; p < 4; p++)
#pragma unroll
        for (int j = 0; j < 8; j++) acc[p][j] = 0ull;

    const float* xb = d_xpad + (long)b * CIN * (XR * XW);

#pragma unroll 1
    for (int h = 0; h < 2; h++) {
        const int len = h ? CONV1_KB : CONV1_KA;
        const int off = h ? CONV1_KA : 0;
        if (h) __syncthreads();
        for (int idx = threadIdx.x; idx < 16 * len; idx += 128) {
            const int o = idx / len;
            const int k = idx - o * len;
            wsm[k][o] = w[o * CONV1_K + off + k];
        }
        __syncthreads();

        const int ic0 = h ? 8 : 0;
        const int icn = h ? 7 : 8;
#pragma unroll 1
        for (int ici = 0; ici < icn; ici++) {
            const int ic = ic0 + ici;
#pragma unroll
            for (int ky = 0; ky < 7; ky++) {
                const float* row = xb + ((long)ic * XR + (2 * oy + ky)) * XW;
                const float4 e0 = *(const float4*)(row + 4 * l);
                const float4 e1 = *(const float4*)(row + 4 * l + 4);
                const float4 q0 = *(const float4*)(row + 260 + 4 * l);
                const float4 q1 = *(const float4*)(row + 260 + 4 * l + 4);
                const float E[8] = {e0.x, e0.y, e0.z, e0.w, e1.x, e1.y, e1.z, e1.w};
                const float O[8] = {q0.x, q0.y, q0.z, q0.w, q1.x, q1.y, q1.z, q1.w};
                const int kb = (ici * 7 + ky) * 7;
#pragma unroll
                for (int kx = 0; kx < 7; kx++) {
                    const ulonglong2* wp = (const ulonglong2*)wsm[kb + kx];
                    const ulonglong2 wA = wp[0], wB = wp[1], wC = wp[2], wD = wp[3];
#pragma unroll
                    for (int p = 0; p < 4; p++) {
                        const float v = (kx & 1) ? E[p + ((kx - 1) >> 1)]
                                                 : O[p + (kx >> 1)];
                        const unsigned long long vv = pack2(v);
                        FFMA2_16(acc[p], vv, wA, wB, wC, wD);
                    }
                }
            }
        }
    }

    if (GATING) {
#pragma unroll
        for (int j = 0; j < 8; j++) {
            const int oca = ocg * 16 + 2 * j;
            const int ocb = oca + 1;
            const float sa = bn_gamma[oca] * rsqrtf(bn_var[oca] + 1e-5f);
            const float sb = bn_gamma[ocb] * rsqrtf(bn_var[ocb] + 1e-5f);
            const float ta = bn_beta[oca] - bn_mean[oca] * sa;
            const float tb = bn_beta[ocb] - bn_mean[ocb] * sb;
            float4 va, vb;
            va.x = fmaxf(f2lo(acc[0][j]) * sa + ta, 0.f);
            va.y = fmaxf(f2lo(acc[1][j]) * sa + ta, 0.f);
            va.z = fmaxf(f2lo(acc[2][j]) * sa + ta, 0.f);
            va.w = fmaxf(f2lo(acc[3][j]) * sa + ta, 0.f);
            vb.x = fmaxf(f2hi(acc[0][j]) * sb + tb, 0.f);
            vb.y = fmaxf(f2hi(acc[1][j]) * sb + tb, 0.f);
            vb.z = fmaxf(f2hi(acc[2][j]) * sb + tb, 0.f);
            vb.w = fmaxf(f2hi(acc[3][j]) * sb + tb, 0.f);
            *(float4*)(d_gbuf + ((long)(b * C1 + oca) * H1 + oy) * W1 + 4 * l) = va;
            *(float4*)(d_gbuf + ((long)(b * C1 + ocb) * H1 + oy) * W1 + 4 * l) = vb;
        }
    } else {
#pragma unroll
        for (int j = 0; j < 8; j++) {
            const int oca = ocg * 16 + 2 * j;
            const int ocb = oca + 1;
            const float fa0 = fmaxf(f2lo(acc[0][j]), 0.f);
            const float fa1 = fmaxf(f2lo(acc[1][j]), 0.f);
            const float fa2 = fmaxf(f2lo(acc[2][j]), 0.f);
            const float fa3 = fmaxf(f2lo(acc[3][j]), 0.f);
            const float fb0 = fmaxf(f2hi(acc[0][j]), 0.f);
            const float fb1 = fmaxf(f2hi(acc[1][j]), 0.f);
            const float fb2 = fmaxf(f2hi(acc[2][j]), 0.f);
            const float fb3 = fmaxf(f2hi(acc[3][j]), 0.f);
            float* ra = d_ebuf1p + ((long)(b * C1 + oca) * E1R + (oy + 1)) * E1W;
            float* rb = d_ebuf1p + ((long)(b * C1 + ocb) * E1R + (oy + 1)) * E1W;
            *(float2*)(ra + 2 * l) = make_float2(fa0, fa2);
            ra[129 + 2 * l] = fa1;  ra[130 + 2 * l] = fa3;
            *(float2*)(rb + 2 * l) = make_float2(fb0, fb2);
            rb[129 + 2 * l] = fb1;  rb[130 + 2 * l] = fb3;
        }
    }
}

// ---------------------------------------------------------------------------
// Kernel 2: maxpool 3x3 s2 pad1 + spatial mean, per (b,c).
// ---------------------------------------------------------------------------
__global__ void pool_mean_kernel()
{
    const int bc = blockIdx.x;
    const float* p = d_gbuf + (long)bc * (H1 * W1);
    float sum = 0.f;
    for (int i = threadIdx.x; i < H2 * W2; i += blockDim.x) {
        const int py = i >> 7, px = i & 127;
        float m = -1e30f;
#pragma unroll
        for (int dy = 0; dy < 3; dy++) {
            const int iy = py * 2 - 1 + dy;
            if ((unsigned)iy >= (unsigned)H1) continue;
            const float* row = p + iy * W1;
#pragma unroll
            for (int dx = 0; dx < 3; dx++) {
                const int ix = px * 2 - 1 + dx;
                if ((unsigned)ix < (unsigned)W1) m = fmaxf(m, row[ix]);
            }
        }
        sum += m;
    }
    __shared__ float red[256];
    red[threadIdx.x] = sum;
    __syncthreads();
    for (int s = 128; s > 0; s >>= 1) {
        if (threadIdx.x < s) red[threadIdx.x] += red[threadIdx.x + s];
        __syncthreads();
    }
    if (threadIdx.x == 0) d_pooled[bc] = red[0] * (1.f / (H2 * W2));
}

// ---------------------------------------------------------------------------
// Kernel 3: FC -> logits -> top-1 expert + aux loss.
// ---------------------------------------------------------------------------
__global__ void gate_finalize_kernel(const float* __restrict__ fcw,
                                     const float* __restrict__ fcb,
                                     float* __restrict__ out_loss)
{
    __shared__ float logits[B][NE];
    const int t = threadIdx.x;
    if (t < B * NE) {
        const int b = t / NE, e = t % NE;
        float s = fcb[e];
        const float* pw = fcw + e * C1;
        const float* pp = d_pooled + b * C1;
        for (int i = 0; i < C1; i++) s += pp[i] * pw[i];
        logits[b][e] = s;
    }
    __syncthreads();
    if (t == 0) {
        float dens[NE]  = {0.f, 0.f, 0.f};
        float proxy[NE] = {0.f, 0.f, 0.f};
        for (int b = 0; b < B; b++) {
            int bi = 0;
            for (int e = 1; e < NE; e++)
                if (logits[b][e] > logits[b][bi]) bi = e;
            d_eidx[b] = bi;
            dens[bi] += 1.f / B;
            float mx = logits[b][0];
            for (int e = 1; e < NE; e++) mx = fmaxf(mx, logits[b][e]);
            float ex[NE], sum = 0.f;
            for (int e = 0; e < NE; e++) { ex[e] = expf(logits[b][e] - mx); sum += ex[e]; }
            for (int e = 0; e < NE; e++) proxy[e] += ex[e] / sum * (1.f / B);
        }
        float aux = 0.f;
        for (int e = 0; e < NE; e++) aux += dens[e] * proxy[e];
        *out_loss = 0.01f * aux * (float)NE;
    }
}

// ---------------------------------------------------------------------------
// Kernel 4: 3x3 s2 conv, 64 -> 128, deinterleaved input -> padded ebuf2.
// Block 128 thr = 4 output rows x 32 lanes; lane computes 4 px, 16 oc.
// Grid (32, 8, 8).
// ---------------------------------------------------------------------------
__global__ void __launch_bounds__(128, 5)
conv2_kernel(const float* __restrict__ w_all)
{
    const int oy  = blockIdx.x * 4 + (threadIdx.x >> 5);
    const int ocg = blockIdx.y;
    const int b   = blockIdx.z;
    const int l   = threadIdx.x & 31;

    const float* w = w_all + ((long)d_eidx[b] * C2 + ocg * 16) * CONV2_K;
    __shared__ __align__(16) float wsm[CONV2_K][16];
    for (int idx = threadIdx.x; idx < 16 * CONV2_K; idx += 128) {
        const int o = idx / CONV2_K;
        const int k = idx - o * CONV2_K;
        wsm[k][o] = w[idx];
    }
    __syncthreads();

    unsigned long long acc[4][8];
#pragma unroll
    for (int p = 0; p < 4; p++)
#pragma unroll
        for (int j = 0; j < 8; j++) acc[p][j] = 0ull;

    const float* ib = d_ebuf1p + (long)b * C1 * (E1R * E1W);
#pragma unroll 1
    for (int ic = 0; ic < C1; ic++) {
        const float* xc = ib + (long)ic * (E1R * E1W);
#pragma unroll
        for (int ky = 0; ky < 3; ky++) {
            const float* row = xc + (2 * oy + ky) * E1W;
            const float4 ev = *(const float4*)(row + 4 * l);
            const float4 q0 = *(const float4*)(row + 128 + 4 * l);
            const float4 q1 = *(const float4*)(row + 128 + 4 * l + 4);
            const float E[4] = {ev.x, ev.y, ev.z, ev.w};
            const float O[8] = {q0.x, q0.y, q0.z, q0.w, q1.x, q1.y, q1.z, q1.w};
            const int kb = (ic * 3 + ky) * 3;
#pragma unroll
            for (int kx = 0; kx < 3; kx++) {
                const ulonglong2* wp = (const ulonglong2*)wsm[kb + kx];
                const ulonglong2 wA = wp[0], wB = wp[1], wC = wp[2], wD = wp[3];
#pragma unroll
                for (int p = 0; p < 4; p++) {
                    const float v = (kx == 1) ? E[p] : ((kx == 0) ? O[p] : O[p + 1]);
                    const unsigned long long vv = pack2(v);
                    FFMA2_16(acc[p], vv, wA, wB, wC, wD);
                }
            }
        }
    }

#pragma unroll
    for (int j = 0; j < 8; j++) {
        const int oca = ocg * 16 + 2 * j;
        const int ocb = oca + 1;
        float* ra = d_ebuf2p + ((long)(b * C2 + oca) * E2R + (oy + 1)) * E2W + 1 + 4 * l;
        float* rb = d_ebuf2p + ((long)(b * C2 + ocb) * E2R + (oy + 1)) * E2W + 1 + 4 * l;
        ra[0] = fmaxf(f2lo(acc[0][j]), 0.f);
        ra[1] = fmaxf(f2lo(acc[1][j]), 0.f);
        ra[2] = fmaxf(f2lo(acc[2][j]), 0.f);
        ra[3] = fmaxf(f2lo(acc[3][j]), 0.f);
        rb[0] = fmaxf(f2hi(acc[0][j]), 0.f);
        rb[1] = fmaxf(f2hi(acc[1][j]), 0.f);
        rb[2] = fmaxf(f2hi(acc[2][j]), 0.f);
        rb[3] = fmaxf(f2hi(acc[3][j]), 0.f);
    }
}

// ---------------------------------------------------------------------------
// Kernel 5: 3x3 s1 conv, 128 -> 128, + bias, ReLU.  (AT ROOFLINE — unchanged)
// Block 128 thr = 4 rows x 32 lanes; lane computes 4 px, 16 oc.
// Weights staged in TWO 36KB passes over ic halves.  Grid (32, 8, 8).
// ---------------------------------------------------------------------------
__global__ void __launch_bounds__(128, 4)
head1_kernel(const float* __restrict__ w_all,
             const float* __restrict__ b_all)
{
    __shared__ __align__(16) float wsm[HEAD1_KH][16];     // 36864 B
    const int oy  = blockIdx.x * 4 + (threadIdx.x >> 5);
    const int ocg = blockIdx.y;
    const int b   = blockIdx.z;
    const int l   = threadIdx.x & 31;
    const int e   = d_eidx[b];

    const float* wbase = w_all + ((long)e * C2 + ocg * 16) * HEAD1_K;

    unsigned long long acc[4][8];
#pragma unroll
    for (int p = 0; p < 4; p++)
#pragma unroll
        for (int j = 0; j < 8; j++) acc[p][j] = 0ull;

    const float* ib = d_ebuf2p + (long)b * C2 * (E2R * E2W);

#pragma unroll 1
    for (int h = 0; h < 2; h++) {
        if (h) __syncthreads();
        for (int idx = threadIdx.x; idx < 16 * HEAD1_KH; idx += 128) {
            const int o = idx / HEAD1_KH;
            const int k = idx - o * HEAD1_KH;
            wsm[k][o] = wbase[o * HEAD1_K + h * HEAD1_KH + k];
        }
        __syncthreads();

        const int ic0 = h * 64;
#pragma unroll 1
        for (int ici = 0; ici < 64; ici++) {
            const float* xc = ib + (long)(ic0 + ici) * (E2R * E2W);
            float W3[3][8];
#pragma unroll
            for (int r = 0; r < 3; r++) {
                const float4 a = *(const float4*)(xc + (oy + r) * E2W + 4 * l);
                const float4 c = *(const float4*)(xc + (oy + r) * E2W + 4 * l + 4);
                W3[r][0] = a.x; W3[r][1] = a.y; W3[r][2] = a.z; W3[r][3] = a.w;
                W3[r][4] = c.x; W3[r][5] = c.y; W3[r][6] = c.z; W3[r][7] = c.w;
            }
#pragma unroll
            for (int ky = 0; ky < 3; ky++) {
                const int kb = (ici * 3 + ky) * 3;
#pragma unroll
                for (int kx = 0; kx < 3; kx++) {
                    const ulonglong2* wp = (const ulonglong2*)wsm[kb + kx];
                    const ulonglong2 wA = wp[0], wB = wp[1], wC = wp[2], wD = wp[3];
#pragma unroll
                    for (int p = 0; p < 4; p++) {
                        const unsigned long long vv = pack2(W3[ky][p + kx]);
                        FFMA2_16(acc[p], vv, wA, wB, wC, wD);
                    }
                }
            }
        }
    }

#pragma unroll
    for (int j = 0; j < 8; j++) {
        const int oca = ocg * 16 + 2 * j;
        const int ocb = oca + 1;
        const float ba = b_all[e * C2 + oca];
        const float bb = b_all[e * C2 + ocb];
        float4 va, vb;
        va.x = fmaxf(f2lo(acc[0][j]) + ba, 0.f);
        va.y = fmaxf(f2lo(acc[1][j]) + ba, 0.f);
        va.z = fmaxf(f2lo(acc[2][j]) + ba, 0.f);
        va.w = fmaxf(f2lo(acc[3][j]) + ba, 0.f);
        vb.x = fmaxf(f2hi(acc[0][j]) + bb, 0.f);
        vb.y = fmaxf(f2hi(acc[1][j]) + bb, 0.f);
        vb.z = fmaxf(f2hi(acc[2][j]) + bb, 0.f);
        vb.w = fmaxf(f2hi(acc[3][j]) + bb, 0.f);
        *(float4*)(d_ebuf3 + ((long)(b * C2 + oca) * H2 + oy) * W2 + 4 * l) = va;
        *(float4*)(d_ebuf3 + ((long)(b * C2 + ocb) * H2 + oy) * W2 + 4 * l) = vb;
    }
}

// ---------------------------------------------------------------------------
// Kernel 6: 1x1 conv 128 -> 5 + bias, scatter into (hm, wh, reg) layout.
// ---------------------------------------------------------------------------
__global__ void __launch_bounds__(128)
head2_kernel(const float* __restrict__ w_all,
             const float* __restrict__ b_all,
             float* __restrict__ out)
{
    const int oy = blockIdx.x;
    const int b  = blockIdx.y;
    const int ox = threadIdx.x;
    const int e  = d_eidx[b];

    __shared__ __align__(16) float ws[C2][8];
    for (int idx = threadIdx.x; idx < 5 * C2; idx += 128) {
        const int j = idx / C2, ic = idx - j * C2;
        ws[ic][j] = w_all[(long)e * 5 * C2 + idx];
    }
    __syncthreads();

    float acc[5] = {0.f, 0.f, 0.f, 0.f, 0.f};
    const float* ib = d_ebuf3 + (long)b * C2 * H2 * W2 + oy * W2 + ox;
    for (int ic = 0; ic < C2; ic++) {
        const float v = __ldg(ib + ic * (H2 * W2));
        const float4 w4 = *(const float4*)ws[ic];
        acc[0] += v * w4.x;
        acc[1] += v * w4.y;
        acc[2] += v * w4.z;
        acc[3] += v * w4.w;
        acc[4] += v * ws[ic][4];
    }

    const int p  = oy * W2 + ox;
    const int HW = H2 * W2;
    const float* bb = b_all + e * 5;
    out[b * HW + p]                        = acc[0] + bb[0];
    out[B * HW + (b * 2 + 0) * HW + p]     = acc[1] + bb[1];
    out[B * HW + (b * 2 + 1) * HW + p]     = acc[2] + bb[2];
    out[3 * B * HW + (b * 2 + 0) * HW + p] = acc[3] + bb[3];
    out[3 * B * HW + (b * 2 + 1) * HW + p] = acc[4] + bb[4];
}

// ---------------------------------------------------------------------------
// Launch
// ---------------------------------------------------------------------------
extern "C" void kernel_launch(void* const* d_in, const int* in_sizes, int n_in,
                              void* d_out, int out_size)
{
    const float* x        = (const float*)d_in[0];
    const float* g_conv_w = (const float*)d_in[1];
    const float* g_gamma  = (const float*)d_in[2];
    const float* g_beta   = (const float*)d_in[3];
    const float* g_mean   = (const float*)d_in[4];
    const float* g_var    = (const float*)d_in[5];
    const float* g_fc_w   = (const float*)d_in[6];
    const float* g_fc_b   = (const float*)d_in[7];
    const float* e_conv1  = (const float*)d_in[8];
    const float* e_conv2  = (const float*)d_in[9];
    const float* e_hw1    = (const float*)d_in[10];
    const float* e_hb1    = (const float*)d_in[11];
    const float* e_hw2    = (const float*)d_in[12];
    const float* e_hb2    = (const float*)d_in[13];
    float* out = (float*)d_out;

    // 0. Pad/deinterleave input + zero activation halos (single launch)
    prep_kernel<<<PREP_E2, 256>>>(x);
    // 1. Gating conv (7x7 s2) + BN + ReLU
    conv7x7_kernel<true><<<dim3(128, 4, B), 128>>>(g_conv_w, g_gamma, g_beta, g_mean, g_var);
    // 2. Maxpool + global average
    pool_mean_kernel<<<B * C1, 256>>>();
    // 3. Logits, top-1 expert selection, aux loss
    gate_finalize_kernel<<<1, 32>>>(g_fc_w, g_fc_b, out + (out_size - 1));
    // 4. Selected expert conv1 (7x7 s2) + ReLU -> ebuf1p (deinterleaved)
    conv7x7_kernel<false><<<dim3(128, 4, B), 128>>>(e_conv1, nullptr, nullptr, nullptr, nullptr);
    // 5. Expert conv2 (3x3 s2) + ReLU -> ebuf2p (padded)
    conv2_kernel<<<dim3(32, 8, B), 128>>>(e_conv2);
    // 6. Head conv1 (3x3 s1) + bias + ReLU -> ebuf3 (two-pass weight staging)
    head1_kernel<<<dim3(32, 8, B), 128>>>(e_hw1, e_hb1);
    // 7. Head conv2 (1x1) + bias, scattered to (hm, wh, reg)
    head2_kernel<<<dim3(128, B), 128>>>(e_hw2, e_hb2, out);
}

// round 10
// speedup vs baseline: 1.0878x; 1.0878x over previous
#include <cuda_runtime.h>
#include <cuda_bf16.h>
#include <math.h>

// ---------------------------------------------------------------------------
// Problem constants
// ---------------------------------------------------------------------------
#define B        8
#define CIN      15          // 3*5 after reshape
#define C1       64
#define H0       512
#define W0       512
#define H1       256
#define W1       256
#define C2       128
#define H2       128
#define W2       128
#define NE       3
#define CONV1_K  (CIN*7*7)   // 735
#define CONV2_K  (C1*3*3)    // 576
#define HEAD1_K  (C2*3*3)    // 1152
#define HEAD1_KH (64*3*3)    // 576 (one ic-half)

// Deinterleaved padded input: per row [even 260 | odd 260] floats, 520 rows.
#define XW  520
#define XR  520
// ebuf1 (conv1 out, 256x256) deinterleaved: row = iy+1 (258 rows),
// [even 128 | odd 132] = 260 floats
#define E1R 258
#define E1W 260
// ebuf2 (conv2 out, 128x128) padded plain: 130 rows x 132, interior 1..128
#define E2R 130
#define E2W 132

// ---------------------------------------------------------------------------
// Device scratch
// ---------------------------------------------------------------------------
__device__ __align__(16) float d_xpad  [(long)B*CIN*XR*XW];
__device__ __align__(16) float d_gbuf  [(long)B*C1*H1*W1];
__device__ __align__(16) float d_ebuf1p[(long)B*C1*E1R*E1W];
__device__ __align__(16) float d_ebuf2p[(long)B*C2*E2R*E2W];
__device__ __align__(16) float d_ebuf3 [(long)B*C2*H2*W2];
__device__ float d_pooled[B*C1];
__device__ int   d_eidx[B];

// ---------------------------------------------------------------------------
// Packed f32x2 helpers
// ---------------------------------------------------------------------------
__device__ __forceinline__ unsigned long long pack2(float v) {
    unsigned long long r;
    asm("mov.b64 %0, {%1, %1};" : "=l"(r) : "f"(v));
    return r;
}
__device__ __forceinline__ void ffma2(unsigned long long& d,
                                      unsigned long long a,
                                      unsigned long long b) {
    asm("fma.rn.f32x2 %0, %1, %2, %0;" : "+l"(d) : "l"(a), "l"(b));
}
__device__ __forceinline__ float f2lo(unsigned long long v) {
    return __uint_as_float((unsigned int)v);
}
__device__ __forceinline__ float f2hi(unsigned long long v) {
    return __uint_as_float((unsigned int)(v >> 32));
}

// 8-oc packed FMA: 4 FFMA2 against 2 u64-pairs of weights
#define FFMA2_8(accp, vv, wA, wB) do {                                \
    ffma2((accp)[0], (vv), (wA).x); ffma2((accp)[1], (vv), (wA).y);   \
    ffma2((accp)[2], (vv), (wB).x); ffma2((accp)[3], (vv), (wB).y);   \
} while (0)

// 16-oc packed FMA (head1 keeps the proven 4px x 16oc shape)
#define FFMA2_16(accp, vv, wA, wB, wC, wD) do {                       \
    ffma2((accp)[0], (vv), (wA).x); ffma2((accp)[1], (vv), (wA).y);   \
    ffma2((accp)[2], (vv), (wB).x); ffma2((accp)[3], (vv), (wB).y);   \
    ffma2((accp)[4], (vv), (wC).x); ffma2((accp)[5], (vv), (wC).y);   \
    ffma2((accp)[6], (vv), (wD).x); ffma2((accp)[7], (vv), (wD).y);   \
} while (0)

// ---------------------------------------------------------------------------
// Kernel 0: prep — pad/deinterleave input + zero activation halos (one launch)
// ---------------------------------------------------------------------------
#define PREP_X   (B*CIN*XR)
#define PREP_E1  (PREP_X + B*C1)
#define PREP_E2  (PREP_E1 + B*C2)

__global__ void __launch_bounds__(256)
prep_kernel(const float* __restrict__ x)
{
    const int blk = blockIdx.x;
    const int t   = threadIdx.x;
    if (blk < PREP_X) {
        const int bc = blk / XR;
        const int r  = blk - bc * XR;
        const int iy = r - 3;
        float* dst = d_xpad + (long)blk * XW;
        const bool rowok = (unsigned)iy < (unsigned)H0;
        if (!rowok) {
            for (int c = t; c < XW; c += 256) dst[c] = 0.f;
        } else {
            const float* src = x + (long)bc * (H0 * W0) + (long)iy * W0;
            if (t < 128) {
                const float4 v = *(const float4*)(src + 4 * t);
                dst[1 + 2 * t]       = v.x;   // even plane, e=2t
                dst[2 + 2 * t]       = v.z;   // even plane, e=2t+1
                dst[260 + 2 + 2 * t] = v.y;   // odd plane,  o=2t
                dst[260 + 3 + 2 * t] = v.w;   // odd plane,  o=2t+1
            } else if (t == 128) {
                dst[0] = 0.f; dst[257] = 0.f; dst[258] = 0.f; dst[259] = 0.f;
                dst[260] = 0.f; dst[261] = 0.f; dst[518] = 0.f; dst[519] = 0.f;
            }
        }
    } else if (blk < PREP_E1) {
        float* p = d_ebuf1p + (long)(blk - PREP_X) * (E1R * E1W);
        for (int i = t; i < E1W; i += 256) p[i] = 0.f;      // row 0
        {
            float* r = p + (t + 1) * E1W;                   // rows 1..256
            r[128] = 0.f;
            r[257] = 0.f; r[258] = 0.f; r[259] = 0.f;
        }
    } else {
        float* p = d_ebuf2p + (long)(blk - PREP_E1) * (E2R * E2W);
        for (int i = t; i < E2W; i += 256) {
            p[i] = 0.f;                                     // row 0
            p[129 * E2W + i] = 0.f;                         // row 129
        }
        if (t < 128) {
            float* r = p + (t + 1) * E2W;                   // rows 1..128
            r[0] = 0.f; r[129] = 0.f; r[130] = 0.f; r[131] = 0.f;
        }
    }
}

// ---------------------------------------------------------------------------
// Kernel 1: 7x7 s2 conv, 15 -> 64, deinterleaved padded input.
// Block 128 thr = 4 output rows x 32 lanes; lane computes 8 px, 8 oc.
// Weight smem 23.5KB (single pass).  Grid (64, 8, 8).
// ---------------------------------------------------------------------------
template <bool GATING>
__global__ void __launch_bounds__(128, 4)
conv7x7_kernel(const float* __restrict__ w_all,
               const float* __restrict__ bn_gamma,
               const float* __restrict__ bn_beta,
               const float* __restrict__ bn_mean,
               const float* __restrict__ bn_var)
{
    const int oy  = blockIdx.x * 4 + (threadIdx.x >> 5);   // 0..255
    const int ocg = blockIdx.y;                            // 0..7 (8 oc each)
    const int b   = blockIdx.z;
    const int l   = threadIdx.x & 31;                      // px0 = 8*l

    const float* w = w_all + (long)ocg * 8 * CONV1_K;
    if (!GATING) w += (long)d_eidx[b] * (C1 * CONV1_K);

    __shared__ __align__(16) float wsm[CONV1_K][8];        // 23520 B
    for (int idx = threadIdx.x; idx < 8 * CONV1_K; idx += 128) {
        const int o = idx / CONV1_K;
        const int k = idx - o * CONV1_K;
        wsm[k][o] = w[idx];
    }
    __syncthreads();

    unsigned long long acc[8][4];
#pragma unroll
    for (int p = 0; p < 8; p++)
#pragma unroll
        for (int j = 0; j < 4; j++) acc[p][j] = 0ull;

    const float* xb = d_xpad + (long)b * CIN * (XR * XW);
#pragma unroll 1
    for (int ic = 0; ic < CIN; ic++) {
#pragma unroll 1
        for (int ky = 0; ky < 7; ky++) {
            const float* row = xb + ((long)ic * XR + (2 * oy + ky)) * XW;
            // even plane pos 8l..8l+11  -> E[i] = e = px0-1+i
            const float4 e0 = *(const float4*)(row + 8 * l);
            const float4 e1 = *(const float4*)(row + 8 * l + 4);
            const float4 e2 = *(const float4*)(row + 8 * l + 8);
            // odd plane pos 260+8l..+11 -> O[i] = o = px0-2+i
            const float4 q0 = *(const float4*)(row + 260 + 8 * l);
            const float4 q1 = *(const float4*)(row + 260 + 8 * l + 4);
            const float4 q2 = *(const float4*)(row + 260 + 8 * l + 8);
            const float E[12] = {e0.x, e0.y, e0.z, e0.w, e1.x, e1.y, e1.z, e1.w,
                                 e2.x, e2.y, e2.z, e2.w};
            const float O[12] = {q0.x, q0.y, q0.z, q0.w, q1.x, q1.y, q1.z, q1.w,
                                 q2.x, q2.y, q2.z, q2.w};
            const int kb = (ic * 7 + ky) * 7;
#pragma unroll
            for (int kx = 0; kx < 7; kx++) {
                const ulonglong2* wp = (const ulonglong2*)wsm[kb + kx];
                const ulonglong2 wA = wp[0], wB = wp[1];
#pragma unroll
                for (int p = 0; p < 8; p++) {
                    const float v = (kx & 1) ? E[p + ((kx - 1) >> 1)]
                                             : O[p + (kx >> 1)];
                    const unsigned long long vv = pack2(v);
                    FFMA2_8(acc[p], vv, wA, wB);
                }
            }
        }
    }

    if (GATING) {
#pragma unroll
        for (int j = 0; j < 4; j++) {
            const int oca = ocg * 8 + 2 * j;
            const int ocb = oca + 1;
            const float sa = bn_gamma[oca] * rsqrtf(bn_var[oca] + 1e-5f);
            const float sb = bn_gamma[ocb] * rsqrtf(bn_var[ocb] + 1e-5f);
            const float ta = bn_beta[oca] - bn_mean[oca] * sa;
            const float tb = bn_beta[ocb] - bn_mean[ocb] * sb;
            float4 va0, va1, vb0, vb1;
            va0.x = fmaxf(f2lo(acc[0][j]) * sa + ta, 0.f);
            va0.y = fmaxf(f2lo(acc[1][j]) * sa + ta, 0.f);
            va0.z = fmaxf(f2lo(acc[2][j]) * sa + ta, 0.f);
            va0.w = fmaxf(f2lo(acc[3][j]) * sa + ta, 0.f);
            va1.x = fmaxf(f2lo(acc[4][j]) * sa + ta, 0.f);
            va1.y = fmaxf(f2lo(acc[5][j]) * sa + ta, 0.f);
            va1.z = fmaxf(f2lo(acc[6][j]) * sa + ta, 0.f);
            va1.w = fmaxf(f2lo(acc[7][j]) * sa + ta, 0.f);
            vb0.x = fmaxf(f2hi(acc[0][j]) * sb + tb, 0.f);
            vb0.y = fmaxf(f2hi(acc[1][j]) * sb + tb, 0.f);
            vb0.z = fmaxf(f2hi(acc[2][j]) * sb + tb, 0.f);
            vb0.w = fmaxf(f2hi(acc[3][j]) * sb + tb, 0.f);
            vb1.x = fmaxf(f2hi(acc[4][j]) * sb + tb, 0.f);
            vb1.y = fmaxf(f2hi(acc[5][j]) * sb + tb, 0.f);
            vb1.z = fmaxf(f2hi(acc[6][j]) * sb + tb, 0.f);
            vb1.w = fmaxf(f2hi(acc[7][j]) * sb + tb, 0.f);
            float* pa = d_gbuf + ((long)(b * C1 + oca) * H1 + oy) * W1 + 8 * l;
            float* pb = d_gbuf + ((long)(b * C1 + ocb) * H1 + oy) * W1 + 8 * l;
            *(float4*)(pa)     = va0;  *(float4*)(pa + 4) = va1;
            *(float4*)(pb)     = vb0;  *(float4*)(pb + 4) = vb1;
        }
    } else {
        // deinterleaved store to ebuf1p: even px -> even plane (float4),
        // odd px -> odd plane (4 scalars, 4B-aligned offset 129+4l)
#pragma unroll
        for (int j = 0; j < 4; j++) {
            const int oca = ocg * 8 + 2 * j;
            const int ocb = oca + 1;
            float* ra = d_ebuf1p + ((long)(b * C1 + oca) * E1R + (oy + 1)) * E1W;
            float* rb = d_ebuf1p + ((long)(b * C1 + ocb) * E1R + (oy + 1)) * E1W;
            float4 ea, eb;
            ea.x = fmaxf(f2lo(acc[0][j]), 0.f);   // px0   -> e=4l
            ea.y = fmaxf(f2lo(acc[2][j]), 0.f);   // px0+2 -> e=4l+1
            ea.z = fmaxf(f2lo(acc[4][j]), 0.f);   // px0+4 -> e=4l+2
            ea.w = fmaxf(f2lo(acc[6][j]), 0.f);   // px0+6 -> e=4l+3
            eb.x = fmaxf(f2hi(acc[0][j]), 0.f);
            eb.y = fmaxf(f2hi(acc[2][j]), 0.f);
            eb.z = fmaxf(f2hi(acc[4][j]), 0.f);
            eb.w = fmaxf(f2hi(acc[6][j]), 0.f);
            *(float4*)(ra + 4 * l) = ea;
            *(float4*)(rb + 4 * l) = eb;
            ra[129 + 4 * l] = fmaxf(f2lo(acc[1][j]), 0.f);  // px0+1 -> o=4l
            ra[130 + 4 * l] = fmaxf(f2lo(acc[3][j]), 0.f);
            ra[131 + 4 * l] = fmaxf(f2lo(acc[5][j]), 0.f);
            ra[132 + 4 * l] = fmaxf(f2lo(acc[7][j]), 0.f);
            rb[129 + 4 * l] = fmaxf(f2hi(acc[1][j]), 0.f);
            rb[130 + 4 * l] = fmaxf(f2hi(acc[3][j]), 0.f);
            rb[131 + 4 * l] = fmaxf(f2hi(acc[5][j]), 0.f);
            rb[132 + 4 * l] = fmaxf(f2hi(acc[7][j]), 0.f);
        }
    }
}

// ---------------------------------------------------------------------------
// Kernel 2: maxpool 3x3 s2 pad1 + spatial mean, per (b,c).
// ---------------------------------------------------------------------------
__global__ void pool_mean_kernel()
{
    const int bc = blockIdx.x;
    const float* p = d_gbuf + (long)bc * (H1 * W1);
    float sum = 0.f;
    for (int i = threadIdx.x; i < H2 * W2; i += blockDim.x) {
        const int py = i >> 7, px = i & 127;
        float m = -1e30f;
#pragma unroll
        for (int dy = 0; dy < 3; dy++) {
            const int iy = py * 2 - 1 + dy;
            if ((unsigned)iy >= (unsigned)H1) continue;
            const float* row = p + iy * W1;
#pragma unroll
            for (int dx = 0; dx < 3; dx++) {
                const int ix = px * 2 - 1 + dx;
                if ((unsigned)ix < (unsigned)W1) m = fmaxf(m, row[ix]);
            }
        }
        sum += m;
    }
    __shared__ float red[256];
    red[threadIdx.x] = sum;
    __syncthreads();
    for (int s = 128; s > 0; s >>= 1) {
        if (threadIdx.x < s) red[threadIdx.x] += red[threadIdx.x + s];
        __syncthreads();
    }
    if (threadIdx.x == 0) d_pooled[bc] = red[0] * (1.f / (H2 * W2));
}

// ---------------------------------------------------------------------------
// Kernel 3: FC -> logits -> top-1 expert + aux loss.
// ---------------------------------------------------------------------------
__global__ void gate_finalize_kernel(const float* __restrict__ fcw,
                                     const float* __restrict__ fcb,
                                     float* __restrict__ out_loss)
{
    __shared__ float logits[B][NE];
    const int t = threadIdx.x;
    if (t < B * NE) {
        const int b = t / NE, e = t % NE;
        float s = fcb[e];
        const float* pw = fcw + e * C1;
        const float* pp = d_pooled + b * C1;
        for (int i = 0; i < C1; i++) s += pp[i] * pw[i];
        logits[b][e] = s;
    }
    __syncthreads();
    if (t == 0) {
        float dens[NE]  = {0.f, 0.f, 0.f};
        float proxy[NE] = {0.f, 0.f, 0.f};
        for (int b = 0; b < B; b++) {
            int bi = 0;
            for (int e = 1; e < NE; e++)
                if (logits[b][e] > logits[b][bi]) bi = e;
            d_eidx[b] = bi;
            dens[bi] += 1.f / B;
            float mx = logits[b][0];
            for (int e = 1; e < NE; e++) mx = fmaxf(mx, logits[b][e]);
            float ex[NE], sum = 0.f;
            for (int e = 0; e < NE; e++) { ex[e] = expf(logits[b][e] - mx); sum += ex[e]; }
            for (int e = 0; e < NE; e++) proxy[e] += ex[e] / sum * (1.f / B);
        }
        float aux = 0.f;
        for (int e = 0; e < NE; e++) aux += dens[e] * proxy[e];
        *out_loss = 0.01f * aux * (float)NE;
    }
}

// ---------------------------------------------------------------------------
// Kernel 4: 3x3 s2 conv, 64 -> 128, deinterleaved input -> padded ebuf2.
// Block 128 thr = 8 output rows x 16 lanes; lane computes 8 px, 8 oc.
// Weight smem 18KB.  Grid (16, 16, 8).
// ---------------------------------------------------------------------------
__global__ void __launch_bounds__(128, 4)
conv2_kernel(const float* __restrict__ w_all)
{
    const int oy  = blockIdx.x * 8 + (threadIdx.x >> 4);  // 0..127
    const int ocg = blockIdx.y;                           // 0..15 (8 oc each)
    const int b   = blockIdx.z;
    const int l   = threadIdx.x & 15;                     // px0 = 8*l

    const float* w = w_all + ((long)d_eidx[b] * C2 + ocg * 8) * CONV2_K;
    __shared__ __align__(16) float wsm[CONV2_K][8];       // 18432 B
    for (int idx = threadIdx.x; idx < 8 * CONV2_K; idx += 128) {
        const int o = idx / CONV2_K;
        const int k = idx - o * CONV2_K;
        wsm[k][o] = w[idx];
    }
    __syncthreads();

    unsigned long long acc[8][4];
#pragma unroll
    for (int p = 0; p < 8; p++)
#pragma unroll
        for (int j = 0; j < 4; j++) acc[p][j] = 0ull;

    const float* ib = d_ebuf1p + (long)b * C1 * (E1R * E1W);
#pragma unroll 1
    for (int ic = 0; ic < C1; ic++) {
        const float* xc = ib + (long)ic * (E1R * E1W);
#pragma unroll
        for (int ky = 0; ky < 3; ky++) {
            const float* row = xc + (2 * oy + ky) * E1W;
            // even plane pos 8l..8l+7   -> E[i] = e = px0+i
            const float4 e0 = *(const float4*)(row + 8 * l);
            const float4 e1 = *(const float4*)(row + 8 * l + 4);
            // odd plane pos 128+8l..+11 -> O[i] = o = px0-1+i
            const float4 q0 = *(const float4*)(row + 128 + 8 * l);
            const float4 q1 = *(const float4*)(row + 128 + 8 * l + 4);
            const float4 q2 = *(const float4*)(row + 128 + 8 * l + 8);
            const float E[8]  = {e0.x, e0.y, e0.z, e0.w, e1.x, e1.y, e1.z, e1.w};
            const float O[12] = {q0.x, q0.y, q0.z, q0.w, q1.x, q1.y, q1.z, q1.w,
                                 q2.x, q2.y, q2.z, q2.w};
            const int kb = (ic * 3 + ky) * 3;
#pragma unroll
            for (int kx = 0; kx < 3; kx++) {
                const ulonglong2* wp = (const ulonglong2*)wsm[kb + kx];
                const ulonglong2 wA = wp[0], wB = wp[1];
#pragma unroll
                for (int p = 0; p < 8; p++) {
                    const float v = (kx == 1) ? E[p] : ((kx == 0) ? O[p] : O[p + 1]);
                    const unsigned long long vv = pack2(v);
                    FFMA2_8(acc[p], vv, wA, wB);
                }
            }
        }
    }

#pragma unroll
    for (int j = 0; j < 4; j++) {
        const int oca = ocg * 8 + 2 * j;
        const int ocb = oca + 1;
        float* ra = d_ebuf2p + ((long)(b * C2 + oca) * E2R + (oy + 1)) * E2W + 1 + 8 * l;
        float* rb = d_ebuf2p + ((long)(b * C2 + ocb) * E2R + (oy + 1)) * E2W + 1 + 8 * l;
#pragma unroll
        for (int p = 0; p < 8; p++) {
            ra[p] = fmaxf(f2lo(acc[p][j]), 0.f);
            rb[p] = fmaxf(f2hi(acc[p][j]), 0.f);
        }
    }
}

// ---------------------------------------------------------------------------
// Kernel 5: 3x3 s1 conv, 128 -> 128, + bias, ReLU.  (AT ROOFLINE — unchanged)
// Block 128 thr = 4 rows x 32 lanes; lane computes 4 px, 16 oc.
// Weights staged in TWO 36KB passes over ic halves.  Grid (32, 8, 8).
// ---------------------------------------------------------------------------
__global__ void __launch_bounds__(128, 4)
head1_kernel(const float* __restrict__ w_all,
             const float* __restrict__ b_all)
{
    __shared__ __align__(16) float wsm[HEAD1_KH][16];     // 36864 B
    const int oy  = blockIdx.x * 4 + (threadIdx.x >> 5);
    const int ocg = blockIdx.y;
    const int b   = blockIdx.z;
    const int l   = threadIdx.x & 31;
    const int e   = d_eidx[b];

    const float* wbase = w_all + ((long)e * C2 + ocg * 16) * HEAD1_K;

    unsigned long long acc[4][8];
#pragma unroll
    for (int p = 0; p < 4; p++)
#pragma unroll
        for (int j = 0; j < 8; j++) acc[p][j] = 0ull;

    const float* ib = d_ebuf2p + (long)b * C2 * (E2R * E2W);

#pragma unroll 1
    for (int h = 0; h < 2; h++) {
        if (h) __syncthreads();
        for (int idx = threadIdx.x; idx < 16 * HEAD1_KH; idx += 128) {
            const int o = idx / HEAD1_KH;
            const int k = idx - o * HEAD1_KH;
            wsm[k][o] = wbase[o * HEAD1_K + h * HEAD1_KH + k];
        }
        __syncthreads();

        const int ic0 = h * 64;
#pragma unroll 1
        for (int ici = 0; ici < 64; ici++) {
            const float* xc = ib + (long)(ic0 + ici) * (E2R * E2W);
            float W3[3][8];
#pragma unroll
            for (int r = 0; r < 3; r++) {
                const float4 a = *(const float4*)(xc + (oy + r) * E2W + 4 * l);
                const float4 c = *(const float4*)(xc + (oy + r) * E2W + 4 * l + 4);
                W3[r][0] = a.x; W3[r][1] = a.y; W3[r][2] = a.z; W3[r][3] = a.w;
                W3[r][4] = c.x; W3[r][5] = c.y; W3[r][6] = c.z; W3[r][7] = c.w;
            }
#pragma unroll
            for (int ky = 0; ky < 3; ky++) {
                const int kb = (ici * 3 + ky) * 3;
#pragma unroll
                for (int kx = 0; kx < 3; kx++) {
                    const ulonglong2* wp = (const ulonglong2*)wsm[kb + kx];
                    const ulonglong2 wA = wp[0], wB = wp[1], wC = wp[2], wD = wp[3];
#pragma unroll
                    for (int p = 0; p < 4; p++) {
                        const unsigned long long vv = pack2(W3[ky][p + kx]);
                        FFMA2_16(acc[p], vv, wA, wB, wC, wD);
                    }
                }
            }
        }
    }

#pragma unroll
    for (int j = 0; j < 8; j++) {
        const int oca = ocg * 16 + 2 * j;
        const int ocb = oca + 1;
        const float ba = b_all[e * C2 + oca];
        const float bb = b_all[e * C2 + ocb];
        float4 va, vb;
        va.x = fmaxf(f2lo(acc[0][j]) + ba, 0.f);
        va.y = fmaxf(f2lo(acc[1][j]) + ba, 0.f);
        va.z = fmaxf(f2lo(acc[2][j]) + ba, 0.f);
        va.w = fmaxf(f2lo(acc[3][j]) + ba, 0.f);
        vb.x = fmaxf(f2hi(acc[0][j]) + bb, 0.f);
        vb.y = fmaxf(f2hi(acc[1][j]) + bb, 0.f);
        vb.z = fmaxf(f2hi(acc[2][j]) + bb, 0.f);
        vb.w = fmaxf(f2hi(acc[3][j]) + bb, 0.f);
        *(float4*)(d_ebuf3 + ((long)(b * C2 + oca) * H2 + oy) * W2 + 4 * l) = va;
        *(float4*)(d_ebuf3 + ((long)(b * C2 + ocb) * H2 + oy) * W2 + 4 * l) = vb;
    }
}

// ---------------------------------------------------------------------------
// Kernel 6: 1x1 conv 128 -> 5 + bias, scatter into (hm, wh, reg) layout.
// ---------------------------------------------------------------------------
__global__ void __launch_bounds__(128)
head2_kernel(const float* __restrict__ w_all,
             const float* __restrict__ b_all,
             float* __restrict__ out)
{
    const int oy = blockIdx.x;
    const int b  = blockIdx.y;
    const int ox = threadIdx.x;
    const int e  = d_eidx[b];

    __shared__ __align__(16) float ws[C2][8];
    for (int idx = threadIdx.x; idx < 5 * C2; idx += 128) {
        const int j = idx / C2, ic = idx - j * C2;
        ws[ic][j] = w_all[(long)e * 5 * C2 + idx];
    }
    __syncthreads();

    float acc[5] = {0.f, 0.f, 0.f, 0.f, 0.f};
    const float* ib = d_ebuf3 + (long)b * C2 * H2 * W2 + oy * W2 + ox;
    for (int ic = 0; ic < C2; ic++) {
        const float v = __ldg(ib + ic * (H2 * W2));
        const float4 w4 = *(const float4*)ws[ic];
        acc[0] += v * w4.x;
        acc[1] += v * w4.y;
        acc[2] += v * w4.z;
        acc[3] += v * w4.w;
        acc[4] += v * ws[ic][4];
    }

    const int p  = oy * W2 + ox;
    const int HW = H2 * W2;
    const float* bb = b_all + e * 5;
    out[b * HW + p]                        = acc[0] + bb[0];
    out[B * HW + (b * 2 + 0) * HW + p]     = acc[1] + bb[1];
    out[B * HW + (b * 2 + 1) * HW + p]     = acc[2] + bb[2];
    out[3 * B * HW + (b * 2 + 0) * HW + p] = acc[3] + bb[3];
    out[3 * B * HW + (b * 2 + 1) * HW + p] = acc[4] + bb[4];
}

// ---------------------------------------------------------------------------
// Launch
// ---------------------------------------------------------------------------
extern "C" void kernel_launch(void* const* d_in, const int* in_sizes, int n_in,
                              void* d_out, int out_size)
{
    const float* x        = (const float*)d_in[0];
    const float* g_conv_w = (const float*)d_in[1];
    const float* g_gamma  = (const float*)d_in[2];
    const float* g_beta   = (const float*)d_in[3];
    const float* g_mean   = (const float*)d_in[4];
    const float* g_var    = (const float*)d_in[5];
    const float* g_fc_w   = (const float*)d_in[6];
    const float* g_fc_b   = (const float*)d_in[7];
    const float* e_conv1  = (const float*)d_in[8];
    const float* e_conv2  = (const float*)d_in[9];
    const float* e_hw1    = (const float*)d_in[10];
    const float* e_hb1    = (const float*)d_in[11];
    const float* e_hw2    = (const float*)d_in[12];
    const float* e_hb2    = (const float*)d_in[13];
    float* out = (float*)d_out;

    // 0. Pad/deinterleave input + zero activation halos (single launch)
    prep_kernel<<<PREP_E2, 256>>>(x);
    // 1. Gating conv (7x7 s2) + BN + ReLU
    conv7x7_kernel<true><<<dim3(64, 8, B), 128>>>(g_conv_w, g_gamma, g_beta, g_mean, g_var);
    // 2. Maxpool + global average
    pool_mean_kernel<<<B * C1, 256>>>();
    // 3. Logits, top-1 expert selection, aux loss
    gate_finalize_kernel<<<1, 32>>>(g_fc_w, g_fc_b, out + (out_size - 1));
    // 4. Selected expert conv1 (7x7 s2) + ReLU -> ebuf1p (deinterleaved)
    conv7x7_kernel<false><<<dim3(64, 8, B), 128>>>(e_conv1, nullptr, nullptr, nullptr, nullptr);
    // 5. Expert conv2 (3x3 s2) + ReLU -> ebuf2p (padded)
    conv2_kernel<<<dim3(16, 16, B), 128>>>(e_conv2);
    // 6. Head conv1 (3x3 s1) + bias + ReLU -> ebuf3 (two-pass weight staging)
    head1_kernel<<<dim3(32, 8, B), 128>>>(e_hw1, e_hb1);
    // 7. Head conv2 (1x1) + bias, scattered to (hm, wh, reg)
    head2_kernel<<<dim3(128, B), 128>>>(e_hw2, e_hb2, out);
}